// round 16
// baseline (speedup 1.0000x reference)
#include <cuda_runtime.h>
#include <math.h>

// GaussianConditionalStanh: y = inputs - means; symbol = searchsorted(mid, y)
// (nearest level in sorted 60-entry codebook, 'left'); dequant = codebook[sym] + means.
// Output layout: [symbols as float (N) | dequant (N)], N = 16*192*96*96.
//
// Near-linear codebook -> arithmetic guess g = round((y-c0)*inv_step) + a
// 4-wide SCALAR probe window [g-2, g+1] over +-inf padded midpoints.
// idx = g-2 + #(mid < y). (Scalar probes beat a float4 table: divergent
// LDS.128 costs >=4 crossbar phases + conflicts — measured R6.)
// R11: all 8 LDG.128 hoisted to the top of the body (MLP_p1=8) so the
// per-thread load pipe never drains between the two compute groups.

#define NLEV 60
#define NMID 59
#define WOFF 4  // padding in front of midpoint array

__global__ void __launch_bounds__(256)
stanh_quant_kernel(const float4* __restrict__ x,
                   const float4* __restrict__ mu,
                   const float* __restrict__ cb,
                   float4* __restrict__ sym_out,
                   float4* __restrict__ deq_out,
                   int n4) {
    __shared__ float pm[WOFF + NMID + 5];  // 68: [-inf x4 | mids x59 | +inf x5]
    __shared__ float scb[NLEV];
    __shared__ float sconst[2];            // inv_step, bias

    int t = threadIdx.x;
    if (t < WOFF + NMID + 5) {
        float v;
        if (t < WOFF)             v = -__int_as_float(0x7f800000);
        else if (t < WOFF + NMID) v = 0.5f * (cb[t - WOFF] + cb[t - WOFF + 1]);
        else                      v = __int_as_float(0x7f800000);
        pm[t] = v;
    }
    if (t < NLEV) scb[t] = cb[t];
    if (t == 0) {
        float c0 = cb[0], cL = cb[NLEV - 1];
        float inv_step = (float)(NLEV - 1) / (cL - c0);
        sconst[0] = inv_step;
        sconst[1] = -c0 * inv_step;
    }
    __syncthreads();

    float inv_step = sconst[0];
    float bias     = sconst[1];

    #define QUANT1(xi, mi, so, dq)                          \
    {                                                       \
        float y = (xi) - (mi);                              \
        int g = __float2int_rn(fmaf(y, inv_step, bias));    \
        g = min(max(g, 0), NLEV - 1);                       \
        int c = 0;                                          \
        c += pm[g + WOFF - 2] < y;                          \
        c += pm[g + WOFF - 1] < y;                          \
        c += pm[g + WOFF + 0] < y;                          \
        c += pm[g + WOFF + 1] < y;                          \
        int idx = g - 2 + c;                                \
        idx = min(max(idx, 0), NLEV - 1);                   \
        (so) = (float)idx;                                  \
        (dq) = scb[idx] + (mi);                             \
    }

    #define QUANT4(xv, mv, sv, dv)                           \
        QUANT1((xv).x, (mv).x, (sv).x, (dv).x);              \
        QUANT1((xv).y, (mv).y, (sv).y, (dv).y);              \
        QUANT1((xv).z, (mv).z, (sv).z, (dv).z);              \
        QUANT1((xv).w, (mv).w, (sv).w, (dv).w);

    // 4 float4 per thread, block-strided for coalescing.
    int base = blockIdx.x * (blockDim.x * 4) + t;
    int i0 = base;
    int i1 = base + blockDim.x;
    int i2 = base + blockDim.x * 2;
    int i3 = base + blockDim.x * 3;

    if (i3 < n4) {
        // All 8 global loads issued back-to-back (MLP_p1 = 8).
        float4 x0 = __ldcs(&x[i0]);
        float4 x1 = __ldcs(&x[i1]);
        float4 x2 = __ldcs(&x[i2]);
        float4 x3 = __ldcs(&x[i3]);
        float4 m0 = __ldcs(&mu[i0]);
        float4 m1 = __ldcs(&mu[i1]);
        float4 m2 = __ldcs(&mu[i2]);
        float4 m3 = __ldcs(&mu[i3]);

        float4 s, d;
        QUANT4(x0, m0, s, d);
        __stcs(&sym_out[i0], s);
        __stcs(&deq_out[i0], d);
        QUANT4(x1, m1, s, d);
        __stcs(&sym_out[i1], s);
        __stcs(&deq_out[i1], d);
        QUANT4(x2, m2, s, d);
        __stcs(&sym_out[i2], s);
        __stcs(&deq_out[i2], d);
        QUANT4(x3, m3, s, d);
        __stcs(&sym_out[i3], s);
        __stcs(&deq_out[i3], d);
    } else {
        // Tail path (only last block)
        #define DO_ONE(ia)                                   \
        if ((ia) < n4) {                                     \
            float4 xa = __ldcs(&x[ia]);                      \
            float4 ma = __ldcs(&mu[ia]);                     \
            float4 sa, da;                                   \
            QUANT4(xa, ma, sa, da);                          \
            __stcs(&sym_out[ia], sa);                        \
            __stcs(&deq_out[ia], da);                        \
        }
        DO_ONE(i0); DO_ONE(i1); DO_ONE(i2); DO_ONE(i3);
        #undef DO_ONE
    }
    #undef QUANT4
    #undef QUANT1
}

extern "C" void kernel_launch(void* const* d_in, const int* in_sizes, int n_in,
                              void* d_out, int out_size) {
    const float* x  = (const float*)d_in[0];   // inputs  [B,C,H,W] f32
    const float* mu = (const float*)d_in[1];   // means   [B,C,H,W] f32
    const float* cb = (const float*)d_in[2];   // codebook [60] f32

    int n  = in_sizes[0];          // 28,311,552 (divisible by 16)
    int n4 = n >> 2;

    float* out = (float*)d_out;
    float* sym = out;              // first N: symbols (as float)
    float* deq = out + n;          // next N: dequant

    int threads = 256;
    int per_block = threads * 4;   // 4 float4 per thread
    int blocks = (n4 + per_block - 1) / per_block;
    stanh_quant_kernel<<<blocks, threads>>>(
        (const float4*)x, (const float4*)mu, cb,
        (float4*)sym, (float4*)deq, n4);
}